// round 1
// baseline (speedup 1.0000x reference)
#include <cuda_runtime.h>
#include <cstdint>
#include <cstddef>

// Problem dims
#define T_STEPS 512
#define B_SZ    128
#define EMB_D   256
#define HID     512
#define GM      16   // batch groups
#define GS      8    // column slices
#define MB      8    // batches per group
#define NJ      64   // columns per slice

// ---------------------------------------------------------------------------
// Scratch (static device memory: no allocation allowed)
// ---------------------------------------------------------------------------
__device__ __align__(16) float g_wx[(size_t)T_STEPS * B_SZ * HID];              // 128 MB
__device__ __align__(16) unsigned long long g_h[2][GM][MB][HID];                 // duplicated f32x2 pairs
__device__ int g_flags[GM * GS];
__device__ int g_xmode;  // 1 = int32 tokens, 2 = int64 tokens (stride in int32 words)

// ---------------------------------------------------------------------------
// f32x2 helpers (FFMA2 path: ptxas will not auto-fuse; PTX only)
// ---------------------------------------------------------------------------
__device__ __forceinline__ unsigned long long pack2(float x) {
    unsigned long long r;
    asm("mov.b64 %0, {%1, %1};" : "=l"(r) : "f"(x));
    return r;
}
__device__ __forceinline__ void ffma2(unsigned long long& d, unsigned long long a, unsigned long long b) {
    asm("fma.rn.f32x2 %0, %1, %2, %0;" : "+l"(d) : "l"(a), "l"(b));
}
__device__ __forceinline__ float2 unpack2(unsigned long long v) {
    float2 f;
    asm("mov.b64 {%0, %1}, %2;" : "=f"(f.x), "=f"(f.y) : "l"(v));
    return f;
}

// ---------------------------------------------------------------------------
// Init: reset sync flags; detect token dtype (int64 high words are all zero)
// ---------------------------------------------------------------------------
__global__ void init_kernel(const int* __restrict__ x32) {
    int tid = threadIdx.x;
    if (tid < GM * GS) g_flags[tid] = 0;
    __shared__ int anynz;
    if (tid == 0) anynz = 0;
    __syncthreads();
    int local = 0;
    for (int i = 2 * tid + 1; i < B_SZ * T_STEPS; i += 2 * blockDim.x) local |= x32[i];
    if (local) atomicOr(&anynz, 1);
    __syncthreads();
    if (tid == 0) g_xmode = anynz ? 1 : 2;
}

// ---------------------------------------------------------------------------
// Kernel A: wx[t,b,j] = Wb[j] + sum_e emb[x[b,t],e] * Ww[j,e]
// Grid: 512 t-tiles x 8 n-tiles.  CTA tile: M=128 (all batches of one t) x N=64, K=256.
// ---------------------------------------------------------------------------
__global__ void __launch_bounds__(256) wx_kernel(const int* __restrict__ x32,
                                                 const float* __restrict__ emb,
                                                 const float* __restrict__ Ww,
                                                 const float* __restrict__ Wb) {
    extern __shared__ float sm[];
    float* A_s = sm;                         // [128][256]
    float* W_s = sm + 128 * EMB_D;           // [256][68]  (WwT, padded)
    __shared__ int tok_s[128];

    const int t   = blockIdx.x >> 3;
    const int n0  = (blockIdx.x & 7) * NJ;
    const int tid = threadIdx.x;
    const int stride = g_xmode;

    if (tid < 128) tok_s[tid] = x32[(size_t)(tid * T_STEPS + t) * stride];
    // WwT load (independent of tok_s)
    for (int i = tid; i < NJ * EMB_D; i += 256) {
        int jl = i >> 8, e = i & 255;
        W_s[e * 68 + jl] = Ww[(size_t)(n0 + jl) * EMB_D + e];
    }
    __syncthreads();
    // Gather A rows (coalesced float4 per emb row segment)
    for (int i4 = tid; i4 < 128 * (EMB_D / 4); i4 += 256) {
        int b = i4 >> 6, e4 = i4 & 63;
        ((float4*)A_s)[i4] = *(const float4*)&emb[(size_t)tok_s[b] * EMB_D + e4 * 4];
    }
    __syncthreads();

    const int mg = tid >> 4, jg = tid & 15;
    const int j0 = 4 * jg;

    unsigned long long acc[8][2];
#pragma unroll
    for (int i = 0; i < 8; i++) { acc[i][0] = 0ULL; acc[i][1] = 0ULL; }

    for (int e0 = 0; e0 < EMB_D; e0 += 4) {
        float4 av[8];
#pragma unroll
        for (int i = 0; i < 8; i++)
            av[i] = *(const float4*)&A_s[(mg * 8 + i) * EMB_D + e0];
#pragma unroll
        for (int q = 0; q < 4; q++) {
            ulonglong2 w = *(const ulonglong2*)&W_s[(e0 + q) * 68 + j0];
#pragma unroll
            for (int i = 0; i < 8; i++) {
                float a = ((const float*)&av[i])[q];
                unsigned long long ad = pack2(a);
                ffma2(acc[i][0], ad, w.x);
                ffma2(acc[i][1], ad, w.y);
            }
        }
    }

    const float4 wb = *(const float4*)&Wb[n0 + j0];
    const size_t base = (size_t)t * B_SZ * HID;
#pragma unroll
    for (int i = 0; i < 8; i++) {
        int b = mg * 8 + i;
        float2 p0 = unpack2(acc[i][0]);
        float2 p1 = unpack2(acc[i][1]);
        float4 o = make_float4(p0.x + wb.x, p0.y + wb.y, p1.x + wb.z, p1.y + wb.w);
        *(float4*)&g_wx[base + (size_t)b * HID + n0 + j0] = o;
    }
}

// ---------------------------------------------------------------------------
// Kernel B: persistent recurrence. 128 CTAs = 16 groups x 8 slices, 1 CTA/SM.
// CTA (g,s): h_{t+1}[b, 64s..64s+64) = tanh(wx[t] + h_t @ UwT_slice + Ub) for
// b in [8g, 8g+8).  h exchanged through L2 with monotonic release/acquire flags.
// ---------------------------------------------------------------------------
__global__ void __launch_bounds__(128) scan_kernel(const float* __restrict__ Uw,
                                                   const float* __restrict__ Ub) {
    extern __shared__ float sm[];
    float* UwT = sm;                                                   // [512][68]
    unsigned long long* hsm = (unsigned long long*)(sm + HID * 68);    // [8][512] dup pairs

    const int tid = threadIdx.x;
    const int g = blockIdx.x >> 3, s = blockIdx.x & 7;

    // Load + transpose Uw slice: UwT[k][jl] = Uw[64s+jl][k]
    for (int i = tid; i < NJ * HID; i += 128) {
        int jl = i >> 9, k = i & 511;
        UwT[k * 68 + jl] = Uw[(size_t)(s * NJ + jl) * HID + k];
    }
    for (int i = tid; i < MB * HID; i += 128) hsm[i] = 0ULL;  // h_0 = 0

    const int b = tid >> 4, jg = tid & 15;
    const int j0 = 4 * jg;
    const int bglob = g * MB + b;
    const float4 ub = *(const float4*)&Ub[s * NJ + j0];
    const int myflag = g * GS + s;
    __syncthreads();

    for (int t = 0; t < T_STEPS; t++) {
        // Prefetch wx for this step (HBM latency hidden under the k-loop)
        const float4 wxv = *(const float4*)&g_wx[((size_t)t * B_SZ + bglob) * HID + s * NJ + j0];

        unsigned long long a00 = 0, a01 = 0, a10 = 0, a11 = 0;
        const unsigned long long* hrow = &hsm[b * HID];
#pragma unroll 2
        for (int k0 = 0; k0 < HID; k0 += 4) {
            ulonglong2 h01 = *(const ulonglong2*)&hrow[k0];
            ulonglong2 h23 = *(const ulonglong2*)&hrow[k0 + 2];
            ulonglong2 w0 = *(const ulonglong2*)&UwT[(k0 + 0) * 68 + j0];
            ulonglong2 w1 = *(const ulonglong2*)&UwT[(k0 + 1) * 68 + j0];
            ulonglong2 w2 = *(const ulonglong2*)&UwT[(k0 + 2) * 68 + j0];
            ulonglong2 w3 = *(const ulonglong2*)&UwT[(k0 + 3) * 68 + j0];
            ffma2(a00, h01.x, w0.x); ffma2(a10, h01.x, w0.y);
            ffma2(a01, h01.y, w1.x); ffma2(a11, h01.y, w1.y);
            ffma2(a00, h23.x, w2.x); ffma2(a10, h23.x, w2.y);
            ffma2(a01, h23.y, w3.x); ffma2(a11, h23.y, w3.y);
        }
        float2 e00 = unpack2(a00), e01 = unpack2(a01);
        float2 e10 = unpack2(a10), e11 = unpack2(a11);
        float o0 = tanhf(e00.x + e01.x + wxv.x + ub.x);
        float o1 = tanhf(e00.y + e01.y + wxv.y + ub.y);
        float o2 = tanhf(e10.x + e11.x + wxv.z + ub.z);
        float o3 = tanhf(e10.y + e11.y + wxv.w + ub.w);

        const int slot = (t + 1) & 1;
        unsigned long long* dst = &g_h[slot][g][b][s * NJ + j0];
        ulonglong2 st0; st0.x = pack2(o0); st0.y = pack2(o1);
        ulonglong2 st1; st1.x = pack2(o2); st1.y = pack2(o3);
        *(ulonglong2*)&dst[0] = st0;
        *(ulonglong2*)&dst[2] = st1;
        __syncthreads();  // all slice STGs issued before the release below
        if (tid == 0) {
            asm volatile("st.release.gpu.global.b32 [%0], %1;"
                         :: "l"(&g_flags[myflag]), "r"(t + 1) : "memory");
        }
        // Wait for all 8 slices of h_{t+1} for this group
        if (tid < GS) {
            const int* fp = &g_flags[g * GS + tid];
            int v;
            do {
                asm volatile("ld.acquire.gpu.global.b32 %0, [%1];" : "=r"(v) : "l"(fp) : "memory");
            } while (v < t + 1);
        }
        __syncthreads();
        // Copy full group h_{t+1} (already in duplicated form) into SMEM
        const ulonglong2* src = (const ulonglong2*)&g_h[slot][g][0][0];
        for (int i = tid; i < MB * HID / 2; i += 128)
            ((ulonglong2*)hsm)[i] = src[i];
        __syncthreads();
    }
}

// ---------------------------------------------------------------------------
// Kernel C: logits[b,o] = Vb[o] + sum_k hT[b,k] * Vw[o,k]   (hT lives in g_h[0])
// ---------------------------------------------------------------------------
__global__ void __launch_bounds__(128) out_kernel(const float* __restrict__ Vw,
                                                  const float* __restrict__ Vb,
                                                  float* __restrict__ out) {
    __shared__ float red0[128], red1[128];
    const int bb = blockIdx.x;
    const unsigned long long* h = &g_h[0][bb >> 3][bb & 7][0];
    const int tid = threadIdx.x;
    float s0 = 0.f, s1 = 0.f;
#pragma unroll
    for (int q = 0; q < 4; q++) {
        int k = tid * 4 + q;
        float hv = unpack2(h[k]).x;
        s0 += hv * Vw[k];
        s1 += hv * Vw[HID + k];
    }
    red0[tid] = s0; red1[tid] = s1;
    __syncthreads();
    for (int off = 64; off > 0; off >>= 1) {
        if (tid < off) { red0[tid] += red0[tid + off]; red1[tid] += red1[tid + off]; }
        __syncthreads();
    }
    if (tid == 0) {
        out[bb * 2 + 0] = red0[0] + Vb[0];
        out[bb * 2 + 1] = red1[0] + Vb[1];
    }
}

// ---------------------------------------------------------------------------
// Launch
// ---------------------------------------------------------------------------
extern "C" void kernel_launch(void* const* d_in, const int* in_sizes, int n_in,
                              void* d_out, int out_size) {
    const int*   x32 = (const int*)d_in[0];
    const float* emb = (const float*)d_in[1];
    const float* Ww  = (const float*)d_in[2];
    const float* Wb  = (const float*)d_in[3];
    const float* Uw  = (const float*)d_in[4];
    const float* Ub  = (const float*)d_in[5];
    const float* Vw  = (const float*)d_in[6];
    const float* Vb  = (const float*)d_in[7];
    float* out = (float*)d_out;

    const int smemA = (128 * EMB_D + EMB_D * 68) * (int)sizeof(float);   // 200704 B
    const int smemB = HID * 68 * (int)sizeof(float) + MB * HID * 8;      // 172032 B
    cudaFuncSetAttribute(wx_kernel,   cudaFuncAttributeMaxDynamicSharedMemorySize, smemA);
    cudaFuncSetAttribute(scan_kernel, cudaFuncAttributeMaxDynamicSharedMemorySize, smemB);

    init_kernel<<<1, 256>>>(x32);
    wx_kernel<<<T_STEPS * 8, 256, smemA>>>(x32, emb, Ww, Wb);
    scan_kernel<<<GM * GS, 128, smemB>>>(Uw, Ub);
    out_kernel<<<B_SZ, 128>>>(Vw, Vb, out);
}

// round 2
// speedup vs baseline: 1.6458x; 1.6458x over previous
#include <cuda_runtime.h>
#include <cstdint>
#include <cstddef>

#define T_STEPS 512
#define B_SZ    128
#define EMB_D   256
#define HID     512
#define GM      16   // batch groups
#define GS      8    // column slices
#define MB      8    // batches per group
#define NJ      64   // columns per slice

// ---------------------------------------------------------------------------
// Static device scratch
// ---------------------------------------------------------------------------
__device__ __align__(16) float g_wx[(size_t)T_STEPS * B_SZ * HID];   // 128 MB
__device__ __align__(16) float g_h[2][GM][HID][MB];                  // [slot][g][j][b] non-dup
__device__ int g_flags[GM * GS];
__device__ int g_xmode;  // 1 = int32 tokens, 2 = int64 tokens

// ---------------------------------------------------------------------------
// f32x2 helpers
// ---------------------------------------------------------------------------
__device__ __forceinline__ unsigned long long pack2(float x) {
    unsigned long long r;
    asm("mov.b64 %0, {%1, %1};" : "=l"(r) : "f"(x));
    return r;
}
__device__ __forceinline__ void ffma2(unsigned long long& d, unsigned long long a, unsigned long long b) {
    asm("fma.rn.f32x2 %0, %1, %2, %0;" : "+l"(d) : "l"(a), "l"(b));
}
__device__ __forceinline__ void add2(unsigned long long& d, unsigned long long a) {
    asm("add.rn.f32x2 %0, %0, %1;" : "+l"(d) : "l"(a));
}
__device__ __forceinline__ float2 unpack2(unsigned long long v) {
    float2 f;
    asm("mov.b64 {%0, %1}, %2;" : "=f"(f.x), "=f"(f.y) : "l"(v));
    return f;
}

// ---------------------------------------------------------------------------
// Init: reset flags; detect token dtype
// ---------------------------------------------------------------------------
__global__ void init_kernel(const int* __restrict__ x32) {
    int tid = threadIdx.x;
    if (tid < GM * GS) g_flags[tid] = 0;
    __shared__ int anynz;
    if (tid == 0) anynz = 0;
    __syncthreads();
    int local = 0;
    for (int i = 2 * tid + 1; i < B_SZ * T_STEPS; i += 2 * blockDim.x) local |= x32[i];
    if (local) atomicOr(&anynz, 1);
    __syncthreads();
    if (tid == 0) g_xmode = anynz ? 1 : 2;
}

// ---------------------------------------------------------------------------
// Kernel A: wx[t,b,j] = Wb[j] + sum_e emb[x[b,t],e] * Ww[j,e]   (unchanged, FFMA-bound)
// ---------------------------------------------------------------------------
__global__ void __launch_bounds__(256) wx_kernel(const int* __restrict__ x32,
                                                 const float* __restrict__ emb,
                                                 const float* __restrict__ Ww,
                                                 const float* __restrict__ Wb) {
    extern __shared__ float sm[];
    float* A_s = sm;                         // [128][256]
    float* W_s = sm + 128 * EMB_D;           // [256][68]
    __shared__ int tok_s[128];

    const int t   = blockIdx.x >> 3;
    const int n0  = (blockIdx.x & 7) * NJ;
    const int tid = threadIdx.x;
    const int stride = g_xmode;

    if (tid < 128) tok_s[tid] = x32[(size_t)(tid * T_STEPS + t) * stride];
    for (int i = tid; i < NJ * EMB_D; i += 256) {
        int jl = i >> 8, e = i & 255;
        W_s[e * 68 + jl] = Ww[(size_t)(n0 + jl) * EMB_D + e];
    }
    __syncthreads();
    for (int i4 = tid; i4 < 128 * (EMB_D / 4); i4 += 256) {
        int b = i4 >> 6, e4 = i4 & 63;
        ((float4*)A_s)[i4] = *(const float4*)&emb[(size_t)tok_s[b] * EMB_D + e4 * 4];
    }
    __syncthreads();

    const int mg = tid >> 4, jg = tid & 15;
    const int j0 = 4 * jg;

    unsigned long long acc[8][2];
#pragma unroll
    for (int i = 0; i < 8; i++) { acc[i][0] = 0ULL; acc[i][1] = 0ULL; }

    for (int e0 = 0; e0 < EMB_D; e0 += 4) {
        float4 av[8];
#pragma unroll
        for (int i = 0; i < 8; i++)
            av[i] = *(const float4*)&A_s[(mg * 8 + i) * EMB_D + e0];
#pragma unroll
        for (int q = 0; q < 4; q++) {
            ulonglong2 w = *(const ulonglong2*)&W_s[(e0 + q) * 68 + j0];
#pragma unroll
            for (int i = 0; i < 8; i++) {
                unsigned long long ad = pack2(((const float*)&av[i])[q]);
                ffma2(acc[i][0], ad, w.x);
                ffma2(acc[i][1], ad, w.y);
            }
        }
    }

    const float4 wb = *(const float4*)&Wb[n0 + j0];
    const size_t base = (size_t)t * B_SZ * HID;
#pragma unroll
    for (int i = 0; i < 8; i++) {
        int b = mg * 8 + i;
        float2 p0 = unpack2(acc[i][0]);
        float2 p1 = unpack2(acc[i][1]);
        float4 o = make_float4(p0.x + wb.x, p0.y + wb.y, p1.x + wb.z, p1.y + wb.w);
        *(float4*)&g_wx[base + (size_t)b * HID + n0 + j0] = o;
    }
}

// ---------------------------------------------------------------------------
// Kernel B: persistent recurrence, crossbar-balanced blocking.
// CTA (g,s): 8 batches x 64 cols. Thread (jg=t&7, ks=t>>3): 8 cols x 8 batches,
// k-range 32. Per k: 2 LDS.128 h + 8 MOV packs + 2 LDS.128 w + 32 FFMA2.
// 16-way k-split reduced through padded smem partial buffer.
// ---------------------------------------------------------------------------
__global__ void __launch_bounds__(128, 1) scan_kernel(const float* __restrict__ Uw,
                                                      const float* __restrict__ Ub) {
    extern __shared__ float sm[];
    float* UwT = sm;                                         // [512][68]
    float* hsm = sm + HID * 68;                              // [512][8]  (h_t, [k][b])
    unsigned long long* P =
        (unsigned long long*)(sm + HID * 68 + HID * MB);     // [32][129] partials

    const int tid = threadIdx.x;
    const int g = blockIdx.x >> 3, s = blockIdx.x & 7;
    const int jg = tid & 7, ks = tid >> 3;
    const int k0 = ks * 32;

    // Load + transpose Uw slice: UwT[k][jl] = Uw[64s+jl][k]
    for (int i = tid; i < NJ * HID; i += 128) {
        int jl = i >> 9, k = i & 511;
        UwT[k * 68 + jl] = Uw[(size_t)(s * NJ + jl) * HID + k];
    }
    for (int i = tid; i < HID * MB; i += 128) hsm[i] = 0.f;   // h_0 = 0

    // Reduce-phase constants: thread tid handles ull-outputs o=2tid, 2tid+1
    const int o    = 2 * tid;
    const int b_r  = o >> 5;                 // local batch 0..7
    const int jpg  = o & 31;                 // even
    const int j0   = 2 * jpg;                // multiple of 4
    const int c0   = 4 * b_r + (jpg & 3);
    const int jg0  = jpg >> 2;
    const int c1   = 4 * b_r + ((jpg + 1) & 3);
    const int jg1  = (jpg + 1) >> 2;
    const int bglob = g * MB + b_r;
    const int myflag = g * GS + s;
    const float4 ub = *(const float4*)&Ub[s * NJ + j0];
    __syncthreads();

    float4 wxv = *(const float4*)&g_wx[((size_t)0 * B_SZ + bglob) * HID + s * NJ + j0];

    for (int t = 0; t < T_STEPS; t++) {
        // ---- k-loop: acc[b][p] over this thread's 32-k range ----
        unsigned long long acc[8][4];
#pragma unroll
        for (int b = 0; b < 8; b++)
#pragma unroll
            for (int p = 0; p < 4; p++) acc[b][p] = 0ULL;

        const float4* hr = (const float4*)&hsm[k0 * MB];
        const float*  wr = &UwT[k0 * 68 + 8 * jg];
#pragma unroll 4
        for (int kk = 0; kk < 32; kk++) {
            float4 ha = hr[2 * kk];
            float4 hb = hr[2 * kk + 1];
            ulonglong2 w0 = *(const ulonglong2*)(wr + kk * 68);
            ulonglong2 w1 = *(const ulonglong2*)(wr + kk * 68 + 4);
            unsigned long long hd;
            hd = pack2(ha.x); ffma2(acc[0][0], hd, w0.x); ffma2(acc[0][1], hd, w0.y);
                              ffma2(acc[0][2], hd, w1.x); ffma2(acc[0][3], hd, w1.y);
            hd = pack2(ha.y); ffma2(acc[1][0], hd, w0.x); ffma2(acc[1][1], hd, w0.y);
                              ffma2(acc[1][2], hd, w1.x); ffma2(acc[1][3], hd, w1.y);
            hd = pack2(ha.z); ffma2(acc[2][0], hd, w0.x); ffma2(acc[2][1], hd, w0.y);
                              ffma2(acc[2][2], hd, w1.x); ffma2(acc[2][3], hd, w1.y);
            hd = pack2(ha.w); ffma2(acc[3][0], hd, w0.x); ffma2(acc[3][1], hd, w0.y);
                              ffma2(acc[3][2], hd, w1.x); ffma2(acc[3][3], hd, w1.y);
            hd = pack2(hb.x); ffma2(acc[4][0], hd, w0.x); ffma2(acc[4][1], hd, w0.y);
                              ffma2(acc[4][2], hd, w1.x); ffma2(acc[4][3], hd, w1.y);
            hd = pack2(hb.y); ffma2(acc[5][0], hd, w0.x); ffma2(acc[5][1], hd, w0.y);
                              ffma2(acc[5][2], hd, w1.x); ffma2(acc[5][3], hd, w1.y);
            hd = pack2(hb.z); ffma2(acc[6][0], hd, w0.x); ffma2(acc[6][1], hd, w0.y);
                              ffma2(acc[6][2], hd, w1.x); ffma2(acc[6][3], hd, w1.y);
            hd = pack2(hb.w); ffma2(acc[7][0], hd, w0.x); ffma2(acc[7][1], hd, w0.y);
                              ffma2(acc[7][2], hd, w1.x); ffma2(acc[7][3], hd, w1.y);
        }

        // ---- store partials (stride-129 pad avoids bank serialization) ----
#pragma unroll
        for (int b = 0; b < 8; b++)
#pragma unroll
            for (int p = 0; p < 4; p++)
                P[(b * 4 + p) * 129 + tid] = acc[b][p];
        __syncthreads();

        // ---- reduce 16 k-slices for outputs o, o+1 ----
        unsigned long long s0 = P[c0 * 129 + jg0];
        unsigned long long s1 = P[c1 * 129 + jg1];
#pragma unroll
        for (int q = 1; q < 16; q++) {
            add2(s0, P[c0 * 129 + q * 8 + jg0]);
            add2(s1, P[c1 * 129 + q * 8 + jg1]);
        }
        float2 f01 = unpack2(s0);
        float2 f23 = unpack2(s1);
        float o0 = tanhf(f01.x + wxv.x + ub.x);
        float o1 = tanhf(f01.y + wxv.y + ub.y);
        float o2 = tanhf(f23.x + wxv.z + ub.z);
        float o3 = tanhf(f23.y + wxv.w + ub.w);

        // ---- publish h_{t+1} ([j][b] non-dup) ----
        const int slot = (t + 1) & 1;
        float* dst = &g_h[slot][g][0][0];
        dst[(s * NJ + j0 + 0) * MB + b_r] = o0;
        dst[(s * NJ + j0 + 1) * MB + b_r] = o1;
        dst[(s * NJ + j0 + 2) * MB + b_r] = o2;
        dst[(s * NJ + j0 + 3) * MB + b_r] = o3;
        __syncthreads();
        if (tid == 0) {
            asm volatile("st.release.gpu.global.b32 [%0], %1;"
                         :: "l"(&g_flags[myflag]), "r"(t + 1) : "memory");
        }
        // prefetch next step's wx while peers finish
        {
            int tn = (t + 1 < T_STEPS) ? t + 1 : t;
            wxv = *(const float4*)&g_wx[((size_t)tn * B_SZ + bglob) * HID + s * NJ + j0];
        }
        if (tid < GS) {
            const int* fp = &g_flags[g * GS + tid];
            int v;
            do {
                asm volatile("ld.acquire.gpu.global.b32 %0, [%1];" : "=r"(v) : "l"(fp) : "memory");
            } while (v < t + 1);
        }
        __syncthreads();

        // ---- copy group h_{t+1} (16 KB) into hsm ----
        const float4* src = (const float4*)&g_h[slot][g][0][0];
        float4* hd4 = (float4*)hsm;
#pragma unroll
        for (int m = 0; m < 8; m++)
            hd4[tid + 128 * m] = src[tid + 128 * m];
        __syncthreads();
    }
}

// ---------------------------------------------------------------------------
// Kernel C: logits from hT (slot 0: T=512 even)
// ---------------------------------------------------------------------------
__global__ void __launch_bounds__(128) out_kernel(const float* __restrict__ Vw,
                                                  const float* __restrict__ Vb,
                                                  float* __restrict__ out) {
    __shared__ float red0[128], red1[128];
    const int bb = blockIdx.x;
    const int g = bb >> 3, bl = bb & 7;
    const float* h = &g_h[0][g][0][0];   // [512][8]
    const int tid = threadIdx.x;
    float s0 = 0.f, s1 = 0.f;
#pragma unroll
    for (int q = 0; q < 4; q++) {
        int k = tid * 4 + q;
        float hv = h[k * MB + bl];
        s0 += hv * Vw[k];
        s1 += hv * Vw[HID + k];
    }
    red0[tid] = s0; red1[tid] = s1;
    __syncthreads();
    for (int off = 64; off > 0; off >>= 1) {
        if (tid < off) { red0[tid] += red0[tid + off]; red1[tid] += red1[tid + off]; }
        __syncthreads();
    }
    if (tid == 0) {
        out[bb * 2 + 0] = red0[0] + Vb[0];
        out[bb * 2 + 1] = red1[0] + Vb[1];
    }
}

// ---------------------------------------------------------------------------
// Launch
// ---------------------------------------------------------------------------
extern "C" void kernel_launch(void* const* d_in, const int* in_sizes, int n_in,
                              void* d_out, int out_size) {
    const int*   x32 = (const int*)d_in[0];
    const float* emb = (const float*)d_in[1];
    const float* Ww  = (const float*)d_in[2];
    const float* Wb  = (const float*)d_in[3];
    const float* Uw  = (const float*)d_in[4];
    const float* Ub  = (const float*)d_in[5];
    const float* Vw  = (const float*)d_in[6];
    const float* Vb  = (const float*)d_in[7];
    float* out = (float*)d_out;

    const int smemA = (128 * EMB_D + EMB_D * 68) * (int)sizeof(float);            // 200704
    const int smemB = (HID * 68 + HID * MB) * (int)sizeof(float) + 32 * 129 * 8;  // 188672
    cudaFuncSetAttribute(wx_kernel,   cudaFuncAttributeMaxDynamicSharedMemorySize, smemA);
    cudaFuncSetAttribute(scan_kernel, cudaFuncAttributeMaxDynamicSharedMemorySize, smemB);

    init_kernel<<<1, 256>>>(x32);
    wx_kernel<<<T_STEPS * 8, 256, smemA>>>(x32, emb, Ww, Wb);
    scan_kernel<<<GM * GS, 128, smemB>>>(Uw, Ub);
    out_kernel<<<B_SZ, 128>>>(Vw, Vb, out);
}

// round 3
// speedup vs baseline: 2.4723x; 1.5022x over previous
#include <cuda_runtime.h>
#include <cstdint>
#include <cstddef>

#define T_STEPS 512
#define B_SZ    128
#define EMB_D   256
#define HID     512
#define VOCAB   50257
#define GM      16   // batch groups
#define GS      8    // column slices
#define MB      8    // batches per group
#define NJ      64   // columns per slice
#define PSTR    260  // partial-buffer row stride in ull (== 4 mod 16 -> conflict-free)

// ---------------------------------------------------------------------------
// Static device scratch
// ---------------------------------------------------------------------------
__device__ __align__(16) float g_wx[(size_t)T_STEPS * B_SZ * HID];   // 128 MB
__device__ __align__(16) float g_h[2][GM][HID][MB];                  // [slot][g][j][b]
__device__ int g_flags[GM * GS][32];                                 // 128 B per flag

// ---------------------------------------------------------------------------
// f32x2 helpers
// ---------------------------------------------------------------------------
__device__ __forceinline__ unsigned long long pack2(float x) {
    unsigned long long r;
    asm("mov.b64 %0, {%1, %1};" : "=l"(r) : "f"(x));
    return r;
}
__device__ __forceinline__ void ffma2(unsigned long long& d, unsigned long long a, unsigned long long b) {
    asm("fma.rn.f32x2 %0, %1, %2, %0;" : "+l"(d) : "l"(a), "l"(b));
}
__device__ __forceinline__ void add2(unsigned long long& d, unsigned long long a) {
    asm("add.rn.f32x2 %0, %0, %1;" : "+l"(d) : "l"(a));
}
__device__ __forceinline__ float2 unpack2(unsigned long long v) {
    float2 f;
    asm("mov.b64 {%0, %1}, %2;" : "=f"(f.x), "=f"(f.y) : "l"(v));
    return f;
}

// ---------------------------------------------------------------------------
// Kernel A: wx[t,b,j] = Wb[j] + sum_e emb[x[b,t],e] * Ww[j,e]
// Also: CTA 0 resets sync flags; every CTA detects token dtype locally.
// ---------------------------------------------------------------------------
__global__ void __launch_bounds__(256) wx_kernel(const int* __restrict__ x32,
                                                 const float* __restrict__ emb,
                                                 const float* __restrict__ Ww,
                                                 const float* __restrict__ Wb) {
    extern __shared__ float sm[];
    float* A_s = sm;                         // [128][256]
    float* W_s = sm + 128 * EMB_D;           // [256][68]
    __shared__ int tok_s[128];

    const int t   = blockIdx.x >> 3;
    const int n0  = (blockIdx.x & 7) * NJ;
    const int tid = threadIdx.x;

    if (blockIdx.x == 0 && tid < GM * GS) g_flags[tid][0] = 0;

    // dtype detection over this CTA's own 128 tokens (int64 little-endian:
    // high word 0 and low word a valid token for every position)
    int lo = 0, hi = 0;
    if (tid < 128) {
        size_t idx = (size_t)tid * T_STEPS + t;
        lo = x32[2 * idx];
        hi = x32[2 * idx + 1];
    }
    int ok = (tid < 128) ? (hi == 0 && (unsigned)lo < VOCAB) : 1;
    int is64 = __syncthreads_and(ok);
    if (tid < 128) tok_s[tid] = is64 ? lo : x32[(size_t)tid * T_STEPS + t];

    for (int i = tid; i < NJ * EMB_D; i += 256) {
        int jl = i >> 8, e = i & 255;
        W_s[e * 68 + jl] = Ww[(size_t)(n0 + jl) * EMB_D + e];
    }
    __syncthreads();
    for (int i4 = tid; i4 < 128 * (EMB_D / 4); i4 += 256) {
        int b = i4 >> 6, e4 = i4 & 63;
        ((float4*)A_s)[i4] = *(const float4*)&emb[(size_t)tok_s[b] * EMB_D + e4 * 4];
    }
    __syncthreads();

    const int mg = tid >> 4, jg = tid & 15;
    const int j0 = 4 * jg;

    unsigned long long acc[8][2];
#pragma unroll
    for (int i = 0; i < 8; i++) { acc[i][0] = 0ULL; acc[i][1] = 0ULL; }

    for (int e0 = 0; e0 < EMB_D; e0 += 4) {
        float4 av[8];
#pragma unroll
        for (int i = 0; i < 8; i++)
            av[i] = *(const float4*)&A_s[(mg * 8 + i) * EMB_D + e0];
#pragma unroll
        for (int q = 0; q < 4; q++) {
            ulonglong2 w = *(const ulonglong2*)&W_s[(e0 + q) * 68 + j0];
#pragma unroll
            for (int i = 0; i < 8; i++) {
                unsigned long long ad = pack2(((const float*)&av[i])[q]);
                ffma2(acc[i][0], ad, w.x);
                ffma2(acc[i][1], ad, w.y);
            }
        }
    }

    const float4 wb = *(const float4*)&Wb[n0 + j0];
    const size_t base = (size_t)t * B_SZ * HID;
#pragma unroll
    for (int i = 0; i < 8; i++) {
        int b = mg * 8 + i;
        float2 p0 = unpack2(acc[i][0]);
        float2 p1 = unpack2(acc[i][1]);
        float4 o = make_float4(p0.x + wb.x, p0.y + wb.y, p1.x + wb.z, p1.y + wb.w);
        *(float4*)&g_wx[base + (size_t)b * HID + n0 + j0] = o;
    }
}

// ---------------------------------------------------------------------------
// Kernel B: persistent recurrence (256 threads) + fused output head.
// CTA (g,s): 8 batches x 64 cols. Thread (jg=tid&7, ks=tid>>3): 8 cols x 8
// batches, k-range 16 (32 k-slices). Conflict-free padded partial reduce.
// ---------------------------------------------------------------------------
__global__ void __launch_bounds__(256, 1) scan_kernel(const float* __restrict__ Uw,
                                                      const float* __restrict__ Ub,
                                                      const float* __restrict__ Vw,
                                                      const float* __restrict__ Vb,
                                                      float* __restrict__ out) {
    extern __shared__ float sm[];
    float* UwT = sm;                                         // [512][68]
    float* hsm = sm + HID * 68;                              // [512][8]  h_t as [k][b]
    unsigned long long* P =
        (unsigned long long*)(sm + HID * 68 + HID * MB);     // [32][PSTR]

    const int tid = threadIdx.x;
    const int g = blockIdx.x >> 3, s = blockIdx.x & 7;
    const int jg = tid & 7, ks = tid >> 3;
    const int k0 = ks * 16;

    for (int i = tid; i < NJ * HID; i += 256) {
        int jl = i >> 9, k = i & 511;
        UwT[k * 68 + jl] = Uw[(size_t)(s * NJ + jl) * HID + k];
    }
    for (int i = tid; i < HID * MB; i += 256) hsm[i] = 0.f;   // h_0 = 0

    // Reduce-phase constants: thread tid owns ull-output o = tid
    const int b_r = tid >> 5;                // local batch
    const int jp  = tid & 31;                // column-pair within slice
    const int p_r = jp & 3;
    const int jgr = jp >> 2;
    const int c_r = 4 * b_r + p_r;
    const int rbase = c_r * PSTR + jgr;
    const int bglob = g * MB + b_r;
    const int myflag = g * GS + s;
    const float2 ub = *(const float2*)&Ub[s * NJ + 2 * jp];
    __syncthreads();

    float2 wxv = *(const float2*)&g_wx[((size_t)0 * B_SZ + bglob) * HID + s * NJ + 2 * jp];

    for (int t = 0; t < T_STEPS; t++) {
        // ---- k-loop over this thread's 16-k range ----
        unsigned long long acc[8][4];
#pragma unroll
        for (int b = 0; b < 8; b++)
#pragma unroll
            for (int p = 0; p < 4; p++) acc[b][p] = 0ULL;

        const float4* hr = (const float4*)&hsm[k0 * MB];
        const float*  wr = &UwT[k0 * 68 + 8 * jg];
#pragma unroll
        for (int kk = 0; kk < 16; kk++) {
            float4 ha = hr[2 * kk];
            float4 hb = hr[2 * kk + 1];
            ulonglong2 w0 = *(const ulonglong2*)(wr + kk * 68);
            ulonglong2 w1 = *(const ulonglong2*)(wr + kk * 68 + 4);
            unsigned long long hd;
            hd = pack2(ha.x); ffma2(acc[0][0], hd, w0.x); ffma2(acc[0][1], hd, w0.y);
                              ffma2(acc[0][2], hd, w1.x); ffma2(acc[0][3], hd, w1.y);
            hd = pack2(ha.y); ffma2(acc[1][0], hd, w0.x); ffma2(acc[1][1], hd, w0.y);
                              ffma2(acc[1][2], hd, w1.x); ffma2(acc[1][3], hd, w1.y);
            hd = pack2(ha.z); ffma2(acc[2][0], hd, w0.x); ffma2(acc[2][1], hd, w0.y);
                              ffma2(acc[2][2], hd, w1.x); ffma2(acc[2][3], hd, w1.y);
            hd = pack2(ha.w); ffma2(acc[3][0], hd, w0.x); ffma2(acc[3][1], hd, w0.y);
                              ffma2(acc[3][2], hd, w1.x); ffma2(acc[3][3], hd, w1.y);
            hd = pack2(hb.x); ffma2(acc[4][0], hd, w0.x); ffma2(acc[4][1], hd, w0.y);
                              ffma2(acc[4][2], hd, w1.x); ffma2(acc[4][3], hd, w1.y);
            hd = pack2(hb.y); ffma2(acc[5][0], hd, w0.x); ffma2(acc[5][1], hd, w0.y);
                              ffma2(acc[5][2], hd, w1.x); ffma2(acc[5][3], hd, w1.y);
            hd = pack2(hb.z); ffma2(acc[6][0], hd, w0.x); ffma2(acc[6][1], hd, w0.y);
                              ffma2(acc[6][2], hd, w1.x); ffma2(acc[6][3], hd, w1.y);
            hd = pack2(hb.w); ffma2(acc[7][0], hd, w0.x); ffma2(acc[7][1], hd, w0.y);
                              ffma2(acc[7][2], hd, w1.x); ffma2(acc[7][3], hd, w1.y);
        }

        // ---- store partials (conflict-free: consecutive tid columns) ----
#pragma unroll
        for (int b = 0; b < 8; b++)
#pragma unroll
            for (int p = 0; p < 4; p++)
                P[(b * 4 + p) * PSTR + tid] = acc[b][p];
        __syncthreads();

        // ---- reduce 32 k-slices for output o=tid (4 parallel chains) ----
        unsigned long long s0 = P[rbase + 0 * 8];
        unsigned long long s1 = P[rbase + 1 * 8];
        unsigned long long s2 = P[rbase + 2 * 8];
        unsigned long long s3 = P[rbase + 3 * 8];
#pragma unroll
        for (int q = 4; q < 32; q += 4) {
            add2(s0, P[rbase + (q + 0) * 8]);
            add2(s1, P[rbase + (q + 1) * 8]);
            add2(s2, P[rbase + (q + 2) * 8]);
            add2(s3, P[rbase + (q + 3) * 8]);
        }
        add2(s0, s1); add2(s2, s3); add2(s0, s2);
        float2 f = unpack2(s0);
        float o0 = tanhf(f.x + wxv.x + ub.x);
        float o1 = tanhf(f.y + wxv.y + ub.y);

        // ---- publish h_{t+1} ([j][b]) ----
        const int slot = (t + 1) & 1;
        float* dst = &g_h[slot][g][0][0];
        dst[(s * NJ + 2 * jp + 0) * MB + b_r] = o0;
        dst[(s * NJ + 2 * jp + 1) * MB + b_r] = o1;
        __syncthreads();
        if (tid == 0) {
            asm volatile("st.release.gpu.global.b32 [%0], %1;"
                         :: "l"(&g_flags[myflag][0]), "r"(t + 1) : "memory");
        }
        // prefetch next step's wx
        {
            int tn = (t + 1 < T_STEPS) ? t + 1 : t;
            wxv = *(const float2*)&g_wx[((size_t)tn * B_SZ + bglob) * HID + s * NJ + 2 * jp];
        }
        if (tid < GS) {
            const int* fp = &g_flags[g * GS + tid][0];
            int v;
            do {
                asm volatile("ld.acquire.gpu.global.b32 %0, [%1];" : "=r"(v) : "l"(fp) : "memory");
            } while (v < t + 1);
        }
        __syncthreads();

        // ---- copy group h_{t+1} (16 KB) into hsm ----
        const float4* src = (const float4*)&g_h[slot][g][0][0];
        float4* hd4 = (float4*)hsm;
#pragma unroll
        for (int m = 0; m < 4; m++)
            hd4[tid + 256 * m] = src[tid + 256 * m];
        __syncthreads();
    }

    // ---- fused output head: slice-0 CTAs emit logits for their 8 batches ----
    if (s == 0) {
        const int w = tid >> 5, lane = tid & 31;   // warp w -> batch w
        float s0 = 0.f, s1 = 0.f;
#pragma unroll
        for (int q = 0; q < 16; q++) {
            int k = lane + 32 * q;
            float hv = hsm[k * MB + w];
            s0 += hv * Vw[k];
            s1 += hv * Vw[HID + k];
        }
#pragma unroll
        for (int off = 16; off > 0; off >>= 1) {
            s0 += __shfl_down_sync(0xFFFFFFFFu, s0, off);
            s1 += __shfl_down_sync(0xFFFFFFFFu, s1, off);
        }
        if (lane == 0) {
            out[(g * MB + w) * 2 + 0] = s0 + Vb[0];
            out[(g * MB + w) * 2 + 1] = s1 + Vb[1];
        }
    }
}

// ---------------------------------------------------------------------------
// Launch (2 kernels -> ncu -s 5 -c 1 lands on scan_kernel)
// ---------------------------------------------------------------------------
extern "C" void kernel_launch(void* const* d_in, const int* in_sizes, int n_in,
                              void* d_out, int out_size) {
    const int*   x32 = (const int*)d_in[0];
    const float* emb = (const float*)d_in[1];
    const float* Ww  = (const float*)d_in[2];
    const float* Wb  = (const float*)d_in[3];
    const float* Uw  = (const float*)d_in[4];
    const float* Ub  = (const float*)d_in[5];
    const float* Vw  = (const float*)d_in[6];
    const float* Vb  = (const float*)d_in[7];
    float* out = (float*)d_out;

    const int smemA = (128 * EMB_D + EMB_D * 68) * (int)sizeof(float);            // 200704
    const int smemB = (HID * 68 + HID * MB) * (int)sizeof(float) + 32 * PSTR * 8; // 222208
    cudaFuncSetAttribute(wx_kernel,   cudaFuncAttributeMaxDynamicSharedMemorySize, smemA);
    cudaFuncSetAttribute(scan_kernel, cudaFuncAttributeMaxDynamicSharedMemorySize, smemB);

    wx_kernel<<<T_STEPS * 8, 256, smemA>>>(x32, emb, Ww, Wb);
    scan_kernel<<<GM * GS, 256, smemB>>>(Uw, Ub, Vw, Vb, out);
}

// round 4
// speedup vs baseline: 2.5948x; 1.0495x over previous
#include <cuda_runtime.h>
#include <cstdint>
#include <cstddef>

#define T_STEPS 512
#define B_SZ    128
#define EMB_D   256
#define HID     512
#define VOCAB   50257
#define GM      16    // batch groups
#define GS      8     // column slices
#define MB      8     // batches per group
#define NJ      64    // columns per slice
#define PSTR    260   // partial row stride (ull), == 4 mod 16 -> conflict-free
#define HSTR    132   // hsm slice stride (floats): 528 B == 16 mod 128
#define WSTR    1092  // UwT slice stride (floats): 4368 B == 16 mod 128

// ---------------------------------------------------------------------------
// Static device scratch
// ---------------------------------------------------------------------------
__device__ __align__(16) float g_wx[(size_t)T_STEPS * B_SZ * HID];   // 128 MB
__device__ __align__(16) float g_h[2][GM][HID][MB];                  // [slot][g][j][b]
__device__ int g_flags[GM * GS][32];                                 // 128 B per flag

// ---------------------------------------------------------------------------
// f32x2 helpers
// ---------------------------------------------------------------------------
__device__ __forceinline__ unsigned long long pack2(float x) {
    unsigned long long r;
    asm("mov.b64 %0, {%1, %1};" : "=l"(r) : "f"(x));
    return r;
}
__device__ __forceinline__ void ffma2(unsigned long long& d, unsigned long long a, unsigned long long b) {
    asm("fma.rn.f32x2 %0, %1, %2, %0;" : "+l"(d) : "l"(a), "l"(b));
}
__device__ __forceinline__ void add2(unsigned long long& d, unsigned long long a) {
    asm("add.rn.f32x2 %0, %0, %1;" : "+l"(d) : "l"(a));
}
__device__ __forceinline__ float2 unpack2(unsigned long long v) {
    float2 f;
    asm("mov.b64 {%0, %1}, %2;" : "=f"(f.x), "=f"(f.y) : "l"(v));
    return f;
}
// tanh(x) = 1 - 2/(e^{2x}+1); MUFU EX2+RCP path, rel err ~1e-6 (budget 1e-3)
__device__ __forceinline__ float fast_tanh(float x) {
    float e = __expf(2.0f * x);
    return 1.0f - __fdividef(2.0f, e + 1.0f);
}

// ---------------------------------------------------------------------------
// Kernel A: wx[t,b,j] = Wb[j] + sum_e emb[x[b,t],e] * Ww[j,e]
// CTA 0 resets flags; every CTA detects token dtype locally.
// ---------------------------------------------------------------------------
__global__ void __launch_bounds__(256) wx_kernel(const int* __restrict__ x32,
                                                 const float* __restrict__ emb,
                                                 const float* __restrict__ Ww,
                                                 const float* __restrict__ Wb) {
    extern __shared__ float sm[];
    float* A_s = sm;                         // [128][256]
    float* W_s = sm + 128 * EMB_D;           // [256][68]
    __shared__ int tok_s[128];

    const int t   = blockIdx.x >> 3;
    const int n0  = (blockIdx.x & 7) * NJ;
    const int tid = threadIdx.x;

    if (blockIdx.x == 0 && tid < GM * GS) g_flags[tid][0] = 0;

    int lo = 0, hi = 0;
    if (tid < 128) {
        size_t idx = (size_t)tid * T_STEPS + t;
        lo = x32[2 * idx];
        hi = x32[2 * idx + 1];
    }
    int ok = (tid < 128) ? (hi == 0 && (unsigned)lo < VOCAB) : 1;
    int is64 = __syncthreads_and(ok);
    if (tid < 128) tok_s[tid] = is64 ? lo : x32[(size_t)tid * T_STEPS + t];

    for (int i = tid; i < NJ * EMB_D; i += 256) {
        int jl = i >> 8, e = i & 255;
        W_s[e * 68 + jl] = Ww[(size_t)(n0 + jl) * EMB_D + e];
    }
    __syncthreads();
    for (int i4 = tid; i4 < 128 * (EMB_D / 4); i4 += 256) {
        int b = i4 >> 6, e4 = i4 & 63;
        ((float4*)A_s)[i4] = *(const float4*)&emb[(size_t)tok_s[b] * EMB_D + e4 * 4];
    }
    __syncthreads();

    const int mg = tid >> 4, jg = tid & 15;
    const int j0 = 4 * jg;

    unsigned long long acc[8][2];
#pragma unroll
    for (int i = 0; i < 8; i++) { acc[i][0] = 0ULL; acc[i][1] = 0ULL; }

    for (int e0 = 0; e0 < EMB_D; e0 += 4) {
        float4 av[8];
#pragma unroll
        for (int i = 0; i < 8; i++)
            av[i] = *(const float4*)&A_s[(mg * 8 + i) * EMB_D + e0];
#pragma unroll
        for (int q = 0; q < 4; q++) {
            ulonglong2 w = *(const ulonglong2*)&W_s[(e0 + q) * 68 + j0];
#pragma unroll
            for (int i = 0; i < 8; i++) {
                unsigned long long ad = pack2(((const float*)&av[i])[q]);
                ffma2(acc[i][0], ad, w.x);
                ffma2(acc[i][1], ad, w.y);
            }
        }
    }

    const float4 wb = *(const float4*)&Wb[n0 + j0];
    const size_t base = (size_t)t * B_SZ * HID;
#pragma unroll
    for (int i = 0; i < 8; i++) {
        int b = mg * 8 + i;
        float2 p0 = unpack2(acc[i][0]);
        float2 p1 = unpack2(acc[i][1]);
        float4 o = make_float4(p0.x + wb.x, p0.y + wb.y, p1.x + wb.z, p1.y + wb.w);
        *(float4*)&g_wx[base + (size_t)b * HID + n0 + j0] = o;
    }
}

// ---------------------------------------------------------------------------
// Kernel B: persistent recurrence + fused output head.
// CTA (g,s): 8 batches x 64 cols, 256 threads. Thread (jg=tid&7, ks=tid>>3):
// 8 cols x 8 batches over 16 k. Padded slice strides (HSTR/WSTR == 16B mod
// 128B) make every k-loop LDS conflict-free; padded P reduce stays so.
// ---------------------------------------------------------------------------
__global__ void __launch_bounds__(256, 1) scan_kernel(const float* __restrict__ Uw,
                                                      const float* __restrict__ Ub,
                                                      const float* __restrict__ Vw,
                                                      const float* __restrict__ Vb,
                                                      float* __restrict__ out) {
    extern __shared__ float sm[];
    float* UwT = sm;                                           // [32][WSTR]
    float* hsm = sm + 32 * WSTR;                               // [32][HSTR]
    unsigned long long* P =
        (unsigned long long*)(sm + 32 * WSTR + 32 * HSTR);     // [32][PSTR]

    const int tid = threadIdx.x;
    const int g = blockIdx.x >> 3, s = blockIdx.x & 3 | ((blockIdx.x & 7) & 7);  // s = blockIdx.x & 7
    const int s_ = blockIdx.x & 7;
    const int jg = tid & 7, ks = tid >> 3;

    // Load + transpose Uw slice: UwT[slice ks][kk][jl] = Uw[64s+jl][16ks+kk]
    for (int i = tid; i < NJ * HID; i += 256) {
        int jl = i >> 9, k = i & 511;
        UwT[(k >> 4) * WSTR + (k & 15) * 68 + jl] = Uw[(size_t)(s_ * NJ + jl) * HID + k];
    }
    for (int i = tid; i < 32 * HSTR; i += 256) hsm[i] = 0.f;   // h_0 = 0

    // Reduce-phase constants: thread tid owns ull-output o = tid
    const int b_r = tid >> 5;
    const int jp  = tid & 31;
    const int rbase = (4 * b_r + (jp & 3)) * PSTR + (jp >> 2);
    const int bglob = g * MB + b_r;
    const int myflag = g * GS + s_;
    const float2 ub = *(const float2*)&Ub[s_ * NJ + 2 * jp];
    __syncthreads();

    float2 wxv = *(const float2*)&g_wx[((size_t)0 * B_SZ + bglob) * HID + s_ * NJ + 2 * jp];

    for (int t = 0; t < T_STEPS; t++) {
        // ---- k-loop over this thread's 16-k slice ----
        unsigned long long acc[8][4];
#pragma unroll
        for (int b = 0; b < 8; b++)
#pragma unroll
            for (int p = 0; p < 4; p++) acc[b][p] = 0ULL;

        const float4* hr4 = (const float4*)&hsm[ks * HSTR];
        const float*  wr  = &UwT[ks * WSTR + 8 * jg];
#pragma unroll
        for (int kk = 0; kk < 16; kk++) {
            float4 ha = hr4[2 * kk];
            float4 hb = hr4[2 * kk + 1];
            ulonglong2 w0 = *(const ulonglong2*)(wr + kk * 68);
            ulonglong2 w1 = *(const ulonglong2*)(wr + kk * 68 + 4);
            unsigned long long hd;
            hd = pack2(ha.x); ffma2(acc[0][0], hd, w0.x); ffma2(acc[0][1], hd, w0.y);
                              ffma2(acc[0][2], hd, w1.x); ffma2(acc[0][3], hd, w1.y);
            hd = pack2(ha.y); ffma2(acc[1][0], hd, w0.x); ffma2(acc[1][1], hd, w0.y);
                              ffma2(acc[1][2], hd, w1.x); ffma2(acc[1][3], hd, w1.y);
            hd = pack2(ha.z); ffma2(acc[2][0], hd, w0.x); ffma2(acc[2][1], hd, w0.y);
                              ffma2(acc[2][2], hd, w1.x); ffma2(acc[2][3], hd, w1.y);
            hd = pack2(ha.w); ffma2(acc[3][0], hd, w0.x); ffma2(acc[3][1], hd, w0.y);
                              ffma2(acc[3][2], hd, w1.x); ffma2(acc[3][3], hd, w1.y);
            hd = pack2(hb.x); ffma2(acc[4][0], hd, w0.x); ffma2(acc[4][1], hd, w0.y);
                              ffma2(acc[4][2], hd, w1.x); ffma2(acc[4][3], hd, w1.y);
            hd = pack2(hb.y); ffma2(acc[5][0], hd, w0.x); ffma2(acc[5][1], hd, w0.y);
                              ffma2(acc[5][2], hd, w1.x); ffma2(acc[5][3], hd, w1.y);
            hd = pack2(hb.z); ffma2(acc[6][0], hd, w0.x); ffma2(acc[6][1], hd, w0.y);
                              ffma2(acc[6][2], hd, w1.x); ffma2(acc[6][3], hd, w1.y);
            hd = pack2(hb.w); ffma2(acc[7][0], hd, w0.x); ffma2(acc[7][1], hd, w0.y);
                              ffma2(acc[7][2], hd, w1.x); ffma2(acc[7][3], hd, w1.y);
        }

        // ---- store partials (consecutive tid columns: conflict-free) ----
#pragma unroll
        for (int b = 0; b < 8; b++)
#pragma unroll
            for (int p = 0; p < 4; p++)
                P[(b * 4 + p) * PSTR + tid] = acc[b][p];
        __syncthreads();

        // ---- reduce 32 k-slices for output pair o = tid ----
        unsigned long long s0 = P[rbase + 0 * 8];
        unsigned long long s1 = P[rbase + 1 * 8];
        unsigned long long s2 = P[rbase + 2 * 8];
        unsigned long long s3 = P[rbase + 3 * 8];
#pragma unroll
        for (int q = 4; q < 32; q += 4) {
            add2(s0, P[rbase + (q + 0) * 8]);
            add2(s1, P[rbase + (q + 1) * 8]);
            add2(s2, P[rbase + (q + 2) * 8]);
            add2(s3, P[rbase + (q + 3) * 8]);
        }
        add2(s0, s1); add2(s2, s3); add2(s0, s2);
        float2 f = unpack2(s0);
        float o0 = fast_tanh(f.x + wxv.x + ub.x);
        float o1 = fast_tanh(f.y + wxv.y + ub.y);

        // ---- publish h_{t+1} ([j][b]) ----
        const int slot = (t + 1) & 1;
        float* dst = &g_h[slot][g][0][0];
        dst[(s_ * NJ + 2 * jp + 0) * MB + b_r] = o0;
        dst[(s_ * NJ + 2 * jp + 1) * MB + b_r] = o1;
        __syncthreads();
        if (tid == 0) {
            asm volatile("st.release.gpu.global.b32 [%0], %1;"
                         :: "l"(&g_flags[myflag][0]), "r"(t + 1) : "memory");
        }
        {
            int tn = (t + 1 < T_STEPS) ? t + 1 : t;
            wxv = *(const float2*)&g_wx[((size_t)tn * B_SZ + bglob) * HID + s_ * NJ + 2 * jp];
        }
        if (tid < GS) {
            const int* fp = &g_flags[g * GS + tid][0];
            int v;
            do {
                asm volatile("ld.acquire.gpu.global.b32 %0, [%1];" : "=r"(v) : "l"(fp) : "memory");
            } while (v < t + 1);
        }
        __syncthreads();

        // ---- copy group h_{t+1} (16 KB) into padded hsm ----
        const float4* src = (const float4*)&g_h[slot][g][0][0];
        float4* hd4 = (float4*)hsm;  // HSTR/4 = 33 float4 per slice
#pragma unroll
        for (int m = 0; m < 4; m++) {
            int idx = tid + 256 * m;
            hd4[(idx >> 5) * 33 + (idx & 31)] = src[idx];
        }
        __syncthreads();
    }

    // ---- fused output head: slice-0 CTAs emit logits for their 8 batches ----
    if (s_ == 0) {
        const int w = tid >> 5, lane = tid & 31;
        float a0 = 0.f, a1 = 0.f;
#pragma unroll
        for (int q = 0; q < 16; q++) {
            int k = lane + 32 * q;
            float hv = hsm[(k >> 4) * HSTR + (k & 15) * 8 + w];
            a0 += hv * Vw[k];
            a1 += hv * Vw[HID + k];
        }
#pragma unroll
        for (int off = 16; off > 0; off >>= 1) {
            a0 += __shfl_down_sync(0xFFFFFFFFu, a0, off);
            a1 += __shfl_down_sync(0xFFFFFFFFu, a1, off);
        }
        if (lane == 0) {
            out[(g * MB + w) * 2 + 0] = a0 + Vb[0];
            out[(g * MB + w) * 2 + 1] = a1 + Vb[1];
        }
    }
    (void)g; (void)s;
}

// ---------------------------------------------------------------------------
// Launch
// ---------------------------------------------------------------------------
extern "C" void kernel_launch(void* const* d_in, const int* in_sizes, int n_in,
                              void* d_out, int out_size) {
    const int*   x32 = (const int*)d_in[0];
    const float* emb = (const float*)d_in[1];
    const float* Ww  = (const float*)d_in[2];
    const float* Wb  = (const float*)d_in[3];
    const float* Uw  = (const float*)d_in[4];
    const float* Ub  = (const float*)d_in[5];
    const float* Vw  = (const float*)d_in[6];
    const float* Vb  = (const float*)d_in[7];
    float* out = (float*)d_out;

    const int smemA = (128 * EMB_D + EMB_D * 68) * (int)sizeof(float);              // 200704
    const int smemB = (32 * WSTR + 32 * HSTR) * (int)sizeof(float) + 32 * PSTR * 8; // 223232
    cudaFuncSetAttribute(wx_kernel,   cudaFuncAttributeMaxDynamicSharedMemorySize, smemA);
    cudaFuncSetAttribute(scan_kernel, cudaFuncAttributeMaxDynamicSharedMemorySize, smemB);

    wx_kernel<<<T_STEPS * 8, 256, smemA>>>(x32, emb, Ww, Wb);
    scan_kernel<<<GM * GS, 256, smemB>>>(Uw, Ub, Vw, Vb, out);
}

// round 5
// speedup vs baseline: 2.7067x; 1.0431x over previous
#include <cuda_runtime.h>
#include <cstdint>
#include <cstddef>

#define T_STEPS 512
#define B_SZ    128
#define EMB_D   256
#define HID     512
#define VOCAB   50257
#define GM      16    // batch groups
#define GS      8     // column slices
#define MB      8     // batches per group
#define NJ      64    // columns per slice
// scan smem strides
#define WS      1024  // UwT slice stride (floats): [32][16kk x 64j]
#define HS      132   // hsm slice stride (floats): 528 B == 16 mod 128
#define PS      520   // P row stride (ull): == 8 mod 16

typedef unsigned long long ull;

// ---------------------------------------------------------------------------
// Static device scratch
// ---------------------------------------------------------------------------
__device__ __align__(16) float g_wx[(size_t)T_STEPS * B_SZ * HID];   // 128 MB
__device__ __align__(16) float g_h[2][GM][HID][MB];                  // [slot][g][j][b]
__device__ int g_flags[GM * GS][32];                                 // 128 B per flag

// ---------------------------------------------------------------------------
// f32x2 helpers
// ---------------------------------------------------------------------------
__device__ __forceinline__ ull pack2(float x) {
    ull r;
    asm("mov.b64 %0, {%1, %1};" : "=l"(r) : "f"(x));
    return r;
}
__device__ __forceinline__ void ffma2(ull& d, ull a, ull b) {
    asm("fma.rn.f32x2 %0, %1, %2, %0;" : "+l"(d) : "l"(a), "l"(b));
}
__device__ __forceinline__ void add2(ull& d, ull a) {
    asm("add.rn.f32x2 %0, %0, %1;" : "+l"(d) : "l"(a));
}
__device__ __forceinline__ float2 unpack2(ull v) {
    float2 f;
    asm("mov.b64 {%0, %1}, %2;" : "=f"(f.x), "=f"(f.y) : "l"(v));
    return f;
}
__device__ __forceinline__ float fast_tanh(float x) {
    float e = __expf(2.0f * x);
    return 1.0f - __fdividef(2.0f, e + 1.0f);
}

// ---------------------------------------------------------------------------
// Kernel A: wx[t,b,j] = Wb[j] + sum_e emb[x[b,t],e] * Ww[j,e]  (unchanged)
// ---------------------------------------------------------------------------
__global__ void __launch_bounds__(256) wx_kernel(const int* __restrict__ x32,
                                                 const float* __restrict__ emb,
                                                 const float* __restrict__ Ww,
                                                 const float* __restrict__ Wb) {
    extern __shared__ float sm[];
    float* A_s = sm;                         // [128][256]
    float* W_s = sm + 128 * EMB_D;           // [256][68]
    __shared__ int tok_s[128];

    const int t   = blockIdx.x >> 3;
    const int n0  = (blockIdx.x & 7) * NJ;
    const int tid = threadIdx.x;

    if (blockIdx.x == 0 && tid < GM * GS) g_flags[tid][0] = 0;

    int lo = 0, hi = 0;
    if (tid < 128) {
        size_t idx = (size_t)tid * T_STEPS + t;
        lo = x32[2 * idx];
        hi = x32[2 * idx + 1];
    }
    int ok = (tid < 128) ? (hi == 0 && (unsigned)lo < VOCAB) : 1;
    int is64 = __syncthreads_and(ok);
    if (tid < 128) tok_s[tid] = is64 ? lo : x32[(size_t)tid * T_STEPS + t];

    for (int i = tid; i < NJ * EMB_D; i += 256) {
        int jl = i >> 8, e = i & 255;
        W_s[e * 68 + jl] = Ww[(size_t)(n0 + jl) * EMB_D + e];
    }
    __syncthreads();
    for (int i4 = tid; i4 < 128 * (EMB_D / 4); i4 += 256) {
        int b = i4 >> 6, e4 = i4 & 63;
        ((float4*)A_s)[i4] = *(const float4*)&emb[(size_t)tok_s[b] * EMB_D + e4 * 4];
    }
    __syncthreads();

    const int mg = tid >> 4, jg = tid & 15;
    const int j0 = 4 * jg;

    ull acc[8][2];
#pragma unroll
    for (int i = 0; i < 8; i++) { acc[i][0] = 0ULL; acc[i][1] = 0ULL; }

    for (int e0 = 0; e0 < EMB_D; e0 += 4) {
        float4 av[8];
#pragma unroll
        for (int i = 0; i < 8; i++)
            av[i] = *(const float4*)&A_s[(mg * 8 + i) * EMB_D + e0];
#pragma unroll
        for (int q = 0; q < 4; q++) {
            ulonglong2 w = *(const ulonglong2*)&W_s[(e0 + q) * 68 + j0];
#pragma unroll
            for (int i = 0; i < 8; i++) {
                ull ad = pack2(((const float*)&av[i])[q]);
                ffma2(acc[i][0], ad, w.x);
                ffma2(acc[i][1], ad, w.y);
            }
        }
    }

    const float4 wb = *(const float4*)&Wb[n0 + j0];
    const size_t base = (size_t)t * B_SZ * HID;
#pragma unroll
    for (int i = 0; i < 8; i++) {
        int b = mg * 8 + i;
        float2 p0 = unpack2(acc[i][0]);
        float2 p1 = unpack2(acc[i][1]);
        float4 o = make_float4(p0.x + wb.x, p0.y + wb.y, p1.x + wb.z, p1.y + wb.w);
        *(float4*)&g_wx[base + (size_t)b * HID + n0 + j0] = o;
    }
}

// ---------------------------------------------------------------------------
// Kernel B: persistent recurrence, 512 threads, warp-specialized exchange.
// CTA (g,s): 8 batches x 64 cols. k-loop thread (jg=tid&15, ks=tid>>4):
// 4 cols x 8 batches over 16 k. Reducers = tid<256 (1 output pair each).
// Warps 8-15: per-slice flag poll + slab copy (pipelined across peers).
// ---------------------------------------------------------------------------
__global__ void __launch_bounds__(512, 1) scan_kernel(const float* __restrict__ Uw,
                                                      const float* __restrict__ Ub,
                                                      const float* __restrict__ Vw,
                                                      const float* __restrict__ Vb,
                                                      float* __restrict__ out) {
    extern __shared__ float sm[];
    float* UwT = sm;                                   // [32][WS]   131072 B
    float* hsm = sm + 32 * WS;                         // [32][HS]    16896 B
    ull*   P   = (ull*)(sm + 32 * WS + 32 * HS);       // [16][PS]    66560 B

    const int tid = threadIdx.x;
    const int g = blockIdx.x >> 3, s_ = blockIdx.x & 7;
    const int jg = tid & 15, ks = tid >> 4;

    // UwT[kslice][kk][j] = Uw[64s+j][16*kslice+kk]
    for (int i = tid; i < NJ * HID; i += 512) {
        int jl = i >> 9, k = i & 511;
        UwT[(k >> 4) * WS + (k & 15) * 64 + jl] = Uw[(size_t)(s_ * NJ + jl) * HID + k];
    }
    for (int i = tid; i < 32 * HS; i += 512) hsm[i] = 0.f;   // h_0 = 0

    // Reducer constants (tid < 256): output pair o = (b_r, jp)
    const int b_r = tid >> 5;
    const int jp  = tid & 31;
    const int rbase = (2 * b_r + (jp & 1)) * PS + (jp >> 1);
    const int j0 = s_ * NJ + 2 * jp;
    const int bglob = g * MB + b_r;
    const int myflag = g * GS + s_;
    const float2 ub = (tid < 256) ? *(const float2*)&Ub[j0] : make_float2(0.f, 0.f);
    const int wp = tid >> 5, lane = tid & 31;
    __syncthreads();

    float2 wxv = make_float2(0.f, 0.f);
    if (tid < 256) wxv = *(const float2*)&g_wx[((size_t)0 * B_SZ + bglob) * HID + j0];

    for (int t = 0; t < T_STEPS; t++) {
        // ---- k-loop: 4 cols x 8 batches over 16 k ----
        ull acc[8][2];
#pragma unroll
        for (int b = 0; b < 8; b++) { acc[b][0] = 0ULL; acc[b][1] = 0ULL; }

        const float* hr = &hsm[ks * HS];
        const float* wr = &UwT[ks * WS + 4 * jg];
#pragma unroll
        for (int kk = 0; kk < 16; kk++) {
            float4 ha = *(const float4*)(hr + kk * 8);
            float4 hb = *(const float4*)(hr + kk * 8 + 4);
            ulonglong2 w = *(const ulonglong2*)(wr + kk * 64);
            ull hd;
            hd = pack2(ha.x); ffma2(acc[0][0], hd, w.x); ffma2(acc[0][1], hd, w.y);
            hd = pack2(ha.y); ffma2(acc[1][0], hd, w.x); ffma2(acc[1][1], hd, w.y);
            hd = pack2(ha.z); ffma2(acc[2][0], hd, w.x); ffma2(acc[2][1], hd, w.y);
            hd = pack2(ha.w); ffma2(acc[3][0], hd, w.x); ffma2(acc[3][1], hd, w.y);
            hd = pack2(hb.x); ffma2(acc[4][0], hd, w.x); ffma2(acc[4][1], hd, w.y);
            hd = pack2(hb.y); ffma2(acc[5][0], hd, w.x); ffma2(acc[5][1], hd, w.y);
            hd = pack2(hb.z); ffma2(acc[6][0], hd, w.x); ffma2(acc[6][1], hd, w.y);
            hd = pack2(hb.w); ffma2(acc[7][0], hd, w.x); ffma2(acc[7][1], hd, w.y);
        }

        // ---- partials: P[combo][tid], combo = 2b+u (consecutive-tid: CF) ----
#pragma unroll
        for (int b = 0; b < 8; b++) {
            P[(2 * b + 0) * PS + tid] = acc[b][0];
            P[(2 * b + 1) * PS + tid] = acc[b][1];
        }
        __syncthreads();

        const int slot = (t + 1) & 1;
        if (tid < 256) {
            // ---- reduce 32 k-slices, 4 chains ----
            ull s0 = P[rbase + 16 * 0];
            ull s1 = P[rbase + 16 * 1];
            ull s2 = P[rbase + 16 * 2];
            ull s3 = P[rbase + 16 * 3];
#pragma unroll
            for (int q = 4; q < 32; q += 4) {
                add2(s0, P[rbase + 16 * (q + 0)]);
                add2(s1, P[rbase + 16 * (q + 1)]);
                add2(s2, P[rbase + 16 * (q + 2)]);
                add2(s3, P[rbase + 16 * (q + 3)]);
            }
            add2(s0, s1); add2(s2, s3); add2(s0, s2);
            float2 f = unpack2(s0);
            float o0 = fast_tanh(f.x + wxv.x + ub.x);
            float o1 = fast_tanh(f.y + wxv.y + ub.y);

            // publish to L2 for peers
            float* dst = &g_h[slot][g][0][0];
            dst[(j0 + 0) * MB + b_r] = o0;
            dst[(j0 + 1) * MB + b_r] = o1;
            // own slab straight into hsm (never re-read from L2)
            int haddr = (j0 >> 4) * HS + (j0 & 15) * 8 + b_r;
            hsm[haddr]     = o0;
            hsm[haddr + 8] = o1;
        }
        __syncthreads();

        if (tid == 0) {
            asm volatile("st.release.gpu.global.b32 [%0], %1;"
                         :: "l"(&g_flags[myflag][0]), "r"(t + 1) : "memory");
        }
        if (wp >= 8) {
            // warp (8+sp): wait for peer slice sp, copy its 2 KB slab
            const int sp = wp - 8;
            if (sp != s_) {
                if (lane == 0) {
                    const int* fp = &g_flags[g * GS + sp][0];
                    int v;
                    do {
                        asm volatile("ld.acquire.gpu.global.b32 %0, [%1];"
                                     : "=r"(v) : "l"(fp) : "memory");
                    } while (v < t + 1);
                }
                __syncwarp();
                const float4* src = (const float4*)&g_h[slot][g][0][0];
#pragma unroll
                for (int m = 0; m < 4; m++) {
                    int fidx = lane + 32 * m;
                    float4 v = src[sp * 128 + fidx];
                    int kg = sp * NJ + (fidx >> 1);
                    *(float4*)&hsm[(kg >> 4) * HS + (kg & 15) * 8 + 4 * (fidx & 1)] = v;
                }
            }
        } else if (tid < 256) {
            int tn = (t + 1 < T_STEPS) ? t + 1 : t;
            wxv = *(const float2*)&g_wx[((size_t)tn * B_SZ + bglob) * HID + j0];
        }
        __syncthreads();
    }

    // ---- fused output head: slice-0 CTAs emit logits for their 8 batches ----
    if (s_ == 0 && wp < 8) {
        float a0 = 0.f, a1 = 0.f;
#pragma unroll
        for (int q = 0; q < 16; q++) {
            int k = lane + 32 * q;
            float hv = hsm[(k >> 4) * HS + (k & 15) * 8 + wp];
            a0 += hv * Vw[k];
            a1 += hv * Vw[HID + k];
        }
#pragma unroll
        for (int off = 16; off > 0; off >>= 1) {
            a0 += __shfl_down_sync(0xFFFFFFFFu, a0, off);
            a1 += __shfl_down_sync(0xFFFFFFFFu, a1, off);
        }
        if (lane == 0) {
            out[(g * MB + wp) * 2 + 0] = a0 + Vb[0];
            out[(g * MB + wp) * 2 + 1] = a1 + Vb[1];
        }
    }
}

// ---------------------------------------------------------------------------
// Launch
// ---------------------------------------------------------------------------
extern "C" void kernel_launch(void* const* d_in, const int* in_sizes, int n_in,
                              void* d_out, int out_size) {
    const int*   x32 = (const int*)d_in[0];
    const float* emb = (const float*)d_in[1];
    const float* Ww  = (const float*)d_in[2];
    const float* Wb  = (const float*)d_in[3];
    const float* Uw  = (const float*)d_in[4];
    const float* Ub  = (const float*)d_in[5];
    const float* Vw  = (const float*)d_in[6];
    const float* Vb  = (const float*)d_in[7];
    float* out = (float*)d_out;

    const int smemA = (128 * EMB_D + EMB_D * 68) * (int)sizeof(float);        // 200704
    const int smemB = (32 * WS + 32 * HS) * (int)sizeof(float) + 16 * PS * 8; // 214528
    cudaFuncSetAttribute(wx_kernel,   cudaFuncAttributeMaxDynamicSharedMemorySize, smemA);
    cudaFuncSetAttribute(scan_kernel, cudaFuncAttributeMaxDynamicSharedMemorySize, smemB);

    wx_kernel<<<T_STEPS * 8, 256, smemA>>>(x32, emb, Ww, Wb);
    scan_kernel<<<GM * GS, 512, smemB>>>(Uw, Ub, Vw, Vb, out);
}